// round 6
// baseline (speedup 1.0000x reference)
#include <cuda_runtime.h>
#include <cstdint>
#include <cstddef>

// Problem constants
#define TT   2048      // tokens (B*S)
#define HH   2048      // hidden
#define NE   16        // experts
#define TOPK 6
#define ID   1408      // expert intermediate I
#define I2   2816      // 2*I
#define ISH  2816      // shared intermediate
#define IS2  5632      // 2*ISH
#define NSLOT (TT * TOPK)   // 12288 routed (token,expert) pairs

// ---------------- scratch (device globals; referenced ONLY in device code) --
__device__ float g_buf1[(size_t)NSLOT * I2];   // 138 MB
__device__ float g_buf2[(size_t)NSLOT * ID];   //  69 MB
__device__ int   g_cnt [NE];
__device__ int   g_off [NE];
__device__ int   g_tok [NE * TT];
__device__ float g_wt  [NE * TT];

// ---------------- small kernels --------------------------------------------
__global__ void zero_cnt_kernel() {
    if (threadIdx.x < NE) g_cnt[threadIdx.x] = 0;
}

__global__ void prefix_kernel() {
    if (threadIdx.x == 0) {
        int acc = 0;
        for (int e = 0; e < NE; e++) { g_off[e] = acc; acc += g_cnt[e]; }
    }
}

__global__ void gate_kernel(const float* __restrict__ x,
                            const float* __restrict__ gw) {
    __shared__ float part[256];
    __shared__ float lg[NE];
    const int t   = blockIdx.x;
    const int tid = threadIdx.x;
    const int e   = tid & 15;
    const int c   = tid >> 4;

    const float* xr = x  + (size_t)t * HH;
    const float* wr = gw + (size_t)e * HH;
    float s = 0.f;
    const int h0 = c * 128;
#pragma unroll 8
    for (int h = h0; h < h0 + 128; h += 4) {
        float4 xv = *(const float4*)(xr + h);
        float4 wv = *(const float4*)(wr + h);
        s += xv.x * wv.x + xv.y * wv.y + xv.z * wv.z + xv.w * wv.w;
    }
    part[tid] = s;
    __syncthreads();
    if (tid < NE) {
        float tot = 0.f;
#pragma unroll
        for (int k = 0; k < 16; k++) tot += part[k * 16 + tid];
        lg[tid] = tot;
    }
    __syncthreads();
    if (tid == 0) {
        float mx = lg[0];
#pragma unroll
        for (int i = 1; i < NE; i++) mx = fmaxf(mx, lg[i]);
        float p[NE];
        float den = 0.f;
#pragma unroll
        for (int i = 0; i < NE; i++) { p[i] = expf(lg[i] - mx); den += p[i]; }
        const float inv = 1.f / den;
#pragma unroll
        for (int i = 0; i < NE; i++) p[i] *= inv;

        bool used[NE];
#pragma unroll
        for (int i = 0; i < NE; i++) used[i] = false;
        for (int j = 0; j < TOPK; j++) {
            int   be = 0;
            float bv = -1.f;
            for (int i = 0; i < NE; i++)
                if (!used[i] && p[i] > bv) { bv = p[i]; be = i; }
            used[be] = true;
            const int slot = atomicAdd(&g_cnt[be], 1);
            g_tok[be * TT + slot] = t;
            g_wt [be * TT + slot] = p[be];
        }
    }
}

__global__ void act_shared_kernel() {
    const int t = blockIdx.x;
    const float* row  = g_buf1 + (size_t)t * IS2;
    float*       orow = g_buf2 + (size_t)t * ISH;
    for (int i = threadIdx.x; i < ISH; i += blockDim.x) {
        const float g = row[i];
        const float u = row[i + ISH];
        orow[i] = u * g / (1.f + __expf(-g));
    }
}

__global__ void act_routed_kernel() {
    const int e = blockIdx.y;
    const int s = blockIdx.x;
    if (s >= g_cnt[e]) return;
    const float w = g_wt[e * TT + s];
    const size_t base = (size_t)(g_off[e] + s);
    const float* row  = g_buf1 + base * I2;
    float*       orow = g_buf2 + base * ID;
    for (int i = threadIdx.x; i < ID; i += blockDim.x) {
        const float g = row[i];
        const float u = row[i + ID];
        orow[i] = w * u * g / (1.f + __expf(-g));
    }
}

// ---------------- TF32 mma.sync GEMM:  C[M,N] = A[M,K] * B[N,K]^T -----------
// Block 128x256, warp tile 64x64 (8 warps, 2m x 4n), KT=8 double-buffered.
// Smem rows are 8 words with an XOR swizzle that places k and k+4 adjacent:
//   phys(k, r) = (2*(k&3) + (k>>2)) ^ s(r),  s(r) = ((r&3) ^ ((r>>2)&3)) << 1
// so each mma fragment half is ONE aligned LDS.64 (16 LDS.64 per 32 MMAs),
// conflict-free per 16-lane phase. Inputs rounded to tf32 with cvt.rna (RN).

__device__ __forceinline__ uint32_t tf32r(float f) {
    uint32_t u;
    asm("cvt.rna.tf32.f32 %0, %1;" : "=r"(u) : "f"(f));
    return u;
}

__device__ __forceinline__ void mma8(float* c, const uint32_t* a, const uint32_t* b) {
    asm volatile(
        "mma.sync.aligned.m16n8k8.row.col.f32.tf32.tf32.f32 "
        "{%0,%1,%2,%3},{%4,%5,%6,%7},{%8,%9},{%0,%1,%2,%3};"
        : "+f"(c[0]), "+f"(c[1]), "+f"(c[2]), "+f"(c[3])
        : "r"(a[0]), "r"(a[1]), "r"(a[2]), "r"(a[3]), "r"(b[0]), "r"(b[1]));
}

__device__ __forceinline__ int swz_s(int r) {
    return (((r & 3) ^ ((r >> 2) & 3)) << 1);
}

#define KT 8
#define MB 128
#define NB 256

template <bool GATHER_A, bool SCATTER_C>
__device__ __forceinline__ void mma_core(
        const float* __restrict__ A, int lda,
        const float* __restrict__ B, int ldb,
        float* __restrict__ C, int ldc,
        int K, int M, const int* __restrict__ tl) {
    const int m0 = blockIdx.y * MB;
    if (m0 >= M) return;
    const int n0 = blockIdx.x * NB;

    __shared__ uint32_t As[2][MB][KT];   //  8 KB
    __shared__ uint32_t Bs[2][NB][KT];   // 16 KB

    const int tid  = threadIdx.x;
    const int lane = tid & 31;
    const int warp = tid >> 5;
    const int warp_m = (warp & 1) * 64;
    const int warp_n = (warp >> 1) * 64;

    // ---- staging maps ----
    // A: 128 rows x 8 cols; 2 threads/row, float4 each
    const int rowA = tid >> 1;
    const int lcA  = (tid & 1) * 4;
    const int rA   = m0 + rowA;
    const bool avalid = rA < M;
    const float* aPtr = A;
    if (avalid) {
        const int ar = GATHER_A ? tl[rA] : rA;
        aPtr = A + (size_t)ar * lda + lcA;
    }
    // B: 256 rows x 8 cols; 1 thread/row, 2x float4
    const float* bPtr = B + (size_t)(n0 + tid) * ldb;

    const int sSA = swz_s(rowA);
    const int sSB = swz_s(tid);
    const int selA = lcA >> 2;   // 0 or 1

    float4 ra, rb0, rb1;

#define LDG_TILE(kt)                                                     \
    do {                                                                 \
        const int k0_ = (kt) * KT;                                       \
        ra  = avalid ? *(const float4*)(aPtr + k0_)                      \
                     : make_float4(0.f, 0.f, 0.f, 0.f);                  \
        rb0 = *(const float4*)(bPtr + k0_);                              \
        rb1 = *(const float4*)(bPtr + k0_ + 4);                          \
    } while (0)

#define STS_TILE(buf)                                                    \
    do {                                                                 \
        As[buf][rowA][(0 + selA) ^ sSA] = tf32r(ra.x);                   \
        As[buf][rowA][(2 + selA) ^ sSA] = tf32r(ra.y);                   \
        As[buf][rowA][(4 + selA) ^ sSA] = tf32r(ra.z);                   \
        As[buf][rowA][(6 + selA) ^ sSA] = tf32r(ra.w);                   \
        Bs[buf][tid][(0) ^ sSB] = tf32r(rb0.x);                          \
        Bs[buf][tid][(2) ^ sSB] = tf32r(rb0.y);                          \
        Bs[buf][tid][(4) ^ sSB] = tf32r(rb0.z);                          \
        Bs[buf][tid][(6) ^ sSB] = tf32r(rb0.w);                          \
        Bs[buf][tid][(1) ^ sSB] = tf32r(rb1.x);                          \
        Bs[buf][tid][(3) ^ sSB] = tf32r(rb1.y);                          \
        Bs[buf][tid][(5) ^ sSB] = tf32r(rb1.z);                          \
        Bs[buf][tid][(7) ^ sSB] = tf32r(rb1.w);                          \
    } while (0)

    float acc[4][8][4];
#pragma unroll
    for (int mi = 0; mi < 4; mi++)
#pragma unroll
        for (int ni = 0; ni < 8; ni++)
#pragma unroll
            for (int i = 0; i < 4; i++) acc[mi][ni][i] = 0.f;

    const int q  = lane >> 2;
    const int kb = lane & 3;
    // fragment columns (s depends only on row mod 16 pattern; constant over mi/ni steps of 16/8)
    const int cA0 = (2 * kb) ^ swz_s(warp_m + q);        // rows warp_m+mi*16+q
    const int cA8 = (2 * kb) ^ swz_s(warp_m + q + 8);    // rows +8
    const int cB0 = (2 * kb) ^ swz_s(warp_n + q);        // even ni
    const int cB1 = (2 * kb) ^ swz_s(warp_n + q + 8);    // odd ni

    LDG_TILE(0);
    STS_TILE(0);
    __syncthreads();

    const int nkt = K / KT;
    for (int kt = 0; kt < nkt; kt++) {
        const int cur = kt & 1;
        const bool more = (kt + 1 < nkt);
        if (more) LDG_TILE(kt + 1);

        uint32_t af[4][4];
#pragma unroll
        for (int mi = 0; mi < 4; mi++) {
            const int r = warp_m + mi * 16 + q;
            const uint2 alo = *(const uint2*)&As[cur][r    ][cA0];  // (a0, a2)
            const uint2 ahi = *(const uint2*)&As[cur][r + 8][cA8];  // (a1, a3)
            af[mi][0] = alo.x; af[mi][1] = ahi.x;
            af[mi][2] = alo.y; af[mi][3] = ahi.y;
        }
#pragma unroll
        for (int ni = 0; ni < 8; ni++) {
            const int rn = warp_n + ni * 8 + q;
            const uint2 bv = *(const uint2*)&Bs[cur][rn][(ni & 1) ? cB1 : cB0];
            uint32_t bf[2] = {bv.x, bv.y};
#pragma unroll
            for (int mi = 0; mi < 4; mi++)
                mma8(acc[mi][ni], af[mi], bf);
        }

        if (more) STS_TILE(cur ^ 1);
        __syncthreads();
    }

    // epilogue: c0,c1 at (row, 2kb..2kb+1); c2,c3 at (row+8, same cols)
#pragma unroll
    for (int mi = 0; mi < 4; mi++) {
        const int rlo = m0 + warp_m + mi * 16 + q;
        const int rhi = rlo + 8;
#pragma unroll
        for (int ni = 0; ni < 8; ni++) {
            const int col = n0 + warp_n + ni * 8 + 2 * kb;
            if (rlo < M) {
                const int cr = SCATTER_C ? tl[rlo] : rlo;
                float* cp = C + (size_t)cr * ldc + col;
                if (SCATTER_C) {
                    atomicAdd(cp,     acc[mi][ni][0]);
                    atomicAdd(cp + 1, acc[mi][ni][1]);
                } else {
                    *(float2*)cp = make_float2(acc[mi][ni][0], acc[mi][ni][1]);
                }
            }
            if (rhi < M) {
                const int cr = SCATTER_C ? tl[rhi] : rhi;
                float* cp = C + (size_t)cr * ldc + col;
                if (SCATTER_C) {
                    atomicAdd(cp,     acc[mi][ni][2]);
                    atomicAdd(cp + 1, acc[mi][ni][3]);
                } else {
                    *(float2*)cp = make_float2(acc[mi][ni][2], acc[mi][ni][3]);
                }
            }
        }
    }
#undef LDG_TILE
#undef STS_TILE
}

// ---------------- GEMM wrappers ---------------------------------------------
__global__ void __launch_bounds__(256, 1)
gemm_shared1(const float* __restrict__ x, const float* __restrict__ sw1) {
    mma_core<false, false>(x, HH, sw1, HH, g_buf1, IS2, HH, TT, nullptr);
}

__global__ void __launch_bounds__(256, 1)
gemm_shared2(const float* __restrict__ sw2, float* __restrict__ out) {
    mma_core<false, false>(g_buf2, ISH, sw2, ISH, out, HH, ISH, TT, nullptr);
}

__global__ void __launch_bounds__(256, 1)
gemm_routed1(const float* __restrict__ x, const float* __restrict__ w1) {
    const int e = blockIdx.z;
    mma_core<true, false>(
        x, HH,
        w1 + (size_t)e * I2 * HH, HH,
        g_buf1 + (size_t)g_off[e] * I2, I2,
        HH, g_cnt[e], g_tok + e * TT);
}

__global__ void __launch_bounds__(256, 1)
gemm_routed2(const float* __restrict__ w2, float* __restrict__ out) {
    const int e = blockIdx.z;
    mma_core<false, true>(
        g_buf2 + (size_t)g_off[e] * ID, ID,
        w2 + (size_t)e * HH * ID, ID,
        out, HH,
        ID, g_cnt[e], g_tok + e * TT);
}

// ---------------- launcher: kernel launches ONLY ----------------------------
extern "C" void kernel_launch(void* const* d_in, const int* in_sizes, int n_in,
                              void* d_out, int out_size) {
    const float* x   = (const float*)d_in[0];   // (1,2048,2048)
    const float* gw  = (const float*)d_in[1];   // (16,2048)
    const float* w1  = (const float*)d_in[2];   // (16,2816,2048)
    const float* w2  = (const float*)d_in[3];   // (16,2048,1408)
    const float* sw1 = (const float*)d_in[4];   // (5632,2048)
    const float* sw2 = (const float*)d_in[5];   // (2048,2816)
    float* out = (float*)d_out;                 // (1,2048,2048) fp32
    (void)in_sizes; (void)n_in; (void)out_size;

    // 1) routing
    zero_cnt_kernel<<<1, 32>>>();
    gate_kernel<<<TT, 256>>>(x, gw);
    prefix_kernel<<<1, 32>>>();

    // 2) shared FFN
    gemm_shared1<<<dim3(IS2 / NB, TT / MB, 1), 256>>>(x, sw1);
    act_shared_kernel<<<TT, 256>>>();
    gemm_shared2<<<dim3(HH / NB, TT / MB, 1), 256>>>(sw2, out);

    // 3) routed path
    gemm_routed1<<<dim3(I2 / NB, TT / MB, NE), 256>>>(x, w1);
    act_routed_kernel<<<dim3(TT, NE), 256>>>();
    gemm_routed2<<<dim3(HH / NB, TT / MB, NE), 256>>>(w2, out);
}

// round 7
// speedup vs baseline: 1.2937x; 1.2937x over previous
#include <cuda_runtime.h>
#include <cstdint>
#include <cstddef>

// Problem constants
#define TT   2048      // tokens (B*S)
#define HH   2048      // hidden
#define NE   16        // experts
#define TOPK 6
#define ID   1408      // expert intermediate I
#define I2   2816      // 2*I
#define ISH  2816      // shared intermediate
#define IS2  5632      // 2*ISH
#define NSLOT (TT * TOPK)   // 12288 routed (token,expert) pairs

// ---------------- scratch (device globals; referenced ONLY in device code) --
__device__ float g_buf1[(size_t)NSLOT * I2];   // 138 MB
__device__ float g_buf2[(size_t)NSLOT * ID];   //  69 MB
__device__ int   g_cnt [NE];
__device__ int   g_off [NE];
__device__ int   g_tok [NE * TT];
__device__ float g_wt  [NE * TT];

// ---------------- small kernels --------------------------------------------
__global__ void zero_cnt_kernel() {
    if (threadIdx.x < NE) g_cnt[threadIdx.x] = 0;
}

__global__ void prefix_kernel() {
    if (threadIdx.x == 0) {
        int acc = 0;
        for (int e = 0; e < NE; e++) { g_off[e] = acc; acc += g_cnt[e]; }
    }
}

__global__ void gate_kernel(const float* __restrict__ x,
                            const float* __restrict__ gw) {
    __shared__ float part[256];
    __shared__ float lg[NE];
    const int t   = blockIdx.x;
    const int tid = threadIdx.x;
    const int e   = tid & 15;
    const int c   = tid >> 4;

    const float* xr = x  + (size_t)t * HH;
    const float* wr = gw + (size_t)e * HH;
    float s = 0.f;
    const int h0 = c * 128;
#pragma unroll 8
    for (int h = h0; h < h0 + 128; h += 4) {
        float4 xv = *(const float4*)(xr + h);
        float4 wv = *(const float4*)(wr + h);
        s += xv.x * wv.x + xv.y * wv.y + xv.z * wv.z + xv.w * wv.w;
    }
    part[tid] = s;
    __syncthreads();
    if (tid < NE) {
        float tot = 0.f;
#pragma unroll
        for (int k = 0; k < 16; k++) tot += part[k * 16 + tid];
        lg[tid] = tot;
    }
    __syncthreads();
    if (tid == 0) {
        float mx = lg[0];
#pragma unroll
        for (int i = 1; i < NE; i++) mx = fmaxf(mx, lg[i]);
        float p[NE];
        float den = 0.f;
#pragma unroll
        for (int i = 0; i < NE; i++) { p[i] = expf(lg[i] - mx); den += p[i]; }
        const float inv = 1.f / den;
#pragma unroll
        for (int i = 0; i < NE; i++) p[i] *= inv;

        bool used[NE];
#pragma unroll
        for (int i = 0; i < NE; i++) used[i] = false;
        for (int j = 0; j < TOPK; j++) {
            int   be = 0;
            float bv = -1.f;
            for (int i = 0; i < NE; i++)
                if (!used[i] && p[i] > bv) { bv = p[i]; be = i; }
            used[be] = true;
            const int slot = atomicAdd(&g_cnt[be], 1);
            g_tok[be * TT + slot] = t;
            g_wt [be * TT + slot] = p[be];
        }
    }
}

__global__ void act_shared_kernel() {
    const int t = blockIdx.x;
    const float* row  = g_buf1 + (size_t)t * IS2;
    float*       orow = g_buf2 + (size_t)t * ISH;
    for (int i = threadIdx.x; i < ISH; i += blockDim.x) {
        const float g = row[i];
        const float u = row[i + ISH];
        orow[i] = u * g / (1.f + __expf(-g));
    }
}

__global__ void act_routed_kernel() {
    const int e = blockIdx.y;
    const int s = blockIdx.x;
    if (s >= g_cnt[e]) return;
    const float w = g_wt[e * TT + s];
    const size_t base = (size_t)(g_off[e] + s);
    const float* row  = g_buf1 + base * I2;
    float*       orow = g_buf2 + base * ID;
    for (int i = threadIdx.x; i < ID; i += blockDim.x) {
        const float g = row[i];
        const float u = row[i + ID];
        orow[i] = w * u * g / (1.f + __expf(-g));
    }
}

// ---------------- TF32 mma.sync GEMM:  C[M,N] = A[M,K] * B[N,K]^T -----------
// Block 128x128, 128 threads = 4 warps (2m x 2n), warp tile 64x64, KT=16
// double-buffered. __launch_bounds__(128,2) -> 2 CTAs/SM so one CTA's
// barrier is hidden by the other's warps.
// Smem rows: 16 words = 8 double-word slots. k maps to slot d(k)=(k&3)+4*(k>>3),
// word (k>>2)&1, so (k,k+4) share one aligned 8B slot -> fragment = 1 LDS.64.
// Slot index XOR-swizzled with s(r) = ((r>>1)&1)<<2 | ((r>>2)&1)<<1:
// fragment phases cover all 16 bank-pairs exactly (conflict-free); STS.64 <=2-way.

__device__ __forceinline__ uint32_t tf32r(float f) {
    uint32_t u;
    asm("cvt.rna.tf32.f32 %0, %1;" : "=r"(u) : "f"(f));
    return u;
}

__device__ __forceinline__ void mma8(float* c, const uint32_t* a, const uint32_t* b) {
    asm volatile(
        "mma.sync.aligned.m16n8k8.row.col.f32.tf32.tf32.f32 "
        "{%0,%1,%2,%3},{%4,%5,%6,%7},{%8,%9},{%0,%1,%2,%3};"
        : "+f"(c[0]), "+f"(c[1]), "+f"(c[2]), "+f"(c[3])
        : "r"(a[0]), "r"(a[1]), "r"(a[2]), "r"(a[3]), "r"(b[0]), "r"(b[1]));
}

__device__ __forceinline__ int swz_s(int r) {
    return ((((r) >> 1) & 1) << 2) | ((((r) >> 2) & 1) << 1);
}

#define KT 16
#define MB 128
#define NB 128
#define NTHR 128

template <bool GATHER_A, bool SCATTER_C>
__device__ __forceinline__ void mma_core(
        const float* __restrict__ A, int lda,
        const float* __restrict__ B, int ldb,
        float* __restrict__ C, int ldc,
        int K, int M, const int* __restrict__ tl) {
    const int m0 = blockIdx.y * MB;
    if (m0 >= M) return;
    const int n0 = blockIdx.x * NB;

    __shared__ uint32_t As[2][MB][KT];   // 16 KB
    __shared__ uint32_t Bs[2][NB][KT];   // 16 KB

    const int tid  = threadIdx.x;
    const int lane = tid & 31;
    const int warp = tid >> 5;
    const int warp_m = (warp & 1) * 64;
    const int warp_n = (warp >> 1) * 64;

    // ---- staging: 2 passes of 64 rows; 2 threads/row, k-half g each -------
    const int srow = tid >> 1;          // 0..63
    const int g    = tid & 1;           // which 8-k half this thread stages
    const int kb8  = g * 8;

    const float* aPtr[2];
    const float* bPtr[2];
    bool av[2];
#pragma unroll
    for (int p = 0; p < 2; p++) {
        const int rA = m0 + srow + 64 * p;
        av[p] = rA < M;
        int ar = 0;
        if (av[p]) ar = GATHER_A ? tl[rA] : rA;
        aPtr[p] = A + (size_t)ar * lda + kb8;
        bPtr[p] = B + (size_t)(n0 + srow + 64 * p) * ldb + kb8;
    }
    const int sS[2] = { swz_s(srow), swz_s(srow + 64) };  // same low bits but compute anyway

    float4 ra[2][2], rb[2][2];

#define LDG_TILE(kt)                                                       \
    do {                                                                   \
        const int k0_ = (kt) * KT;                                         \
        _Pragma("unroll")                                                  \
        for (int p = 0; p < 2; p++) {                                      \
            ra[p][0] = av[p] ? *(const float4*)(aPtr[p] + k0_)             \
                             : make_float4(0.f, 0.f, 0.f, 0.f);            \
            ra[p][1] = av[p] ? *(const float4*)(aPtr[p] + k0_ + 4)         \
                             : make_float4(0.f, 0.f, 0.f, 0.f);            \
            rb[p][0] = *(const float4*)(bPtr[p] + k0_);                    \
            rb[p][1] = *(const float4*)(bPtr[p] + k0_ + 4);                \
        }                                                                  \
    } while (0)

    // word0 of slot = k (first float4 comp j), word1 = k+4 (second float4 comp j)
#define STS_TILE(buf)                                                      \
    do {                                                                   \
        _Pragma("unroll")                                                  \
        for (int p = 0; p < 2; p++) {                                      \
            const int rr = srow + 64 * p;                                  \
            const int ss = sS[p];                                          \
            const float* a0 = &ra[p][0].x;                                 \
            const float* a1 = &ra[p][1].x;                                 \
            const float* b0 = &rb[p][0].x;                                 \
            const float* b1 = &rb[p][1].x;                                 \
            _Pragma("unroll")                                              \
            for (int j = 0; j < 4; j++) {                                  \
                const int dw = (j + 4 * g) ^ ss;                           \
                *(uint2*)&As[buf][rr][2 * dw] =                            \
                    make_uint2(tf32r(a0[j]), tf32r(a1[j]));                \
                *(uint2*)&Bs[buf][rr][2 * dw] =                            \
                    make_uint2(tf32r(b0[j]), tf32r(b1[j]));                \
            }                                                              \
        }                                                                  \
    } while (0)

    float acc[4][8][4];
#pragma unroll
    for (int mi = 0; mi < 4; mi++)
#pragma unroll
        for (int ni = 0; ni < 8; ni++)
#pragma unroll
            for (int i = 0; i < 4; i++) acc[mi][ni][i] = 0.f;

    const int q  = lane >> 2;
    const int kb = lane & 3;
    const int sq = swz_s(q);             // rows' low bits == q for all fragments
    const int colStep[2] = { 2 * ((kb    ) ^ sq),
                             2 * ((kb + 4) ^ sq) };

    LDG_TILE(0);
    STS_TILE(0);
    __syncthreads();

    const int nkt = K / KT;
    for (int kt = 0; kt < nkt; kt++) {
        const int cur = kt & 1;
        const bool more = (kt + 1 < nkt);
        if (more) LDG_TILE(kt + 1);

#pragma unroll
        for (int st = 0; st < 2; st++) {
            const int col = colStep[st];
            uint32_t af[4][4];
#pragma unroll
            for (int mi = 0; mi < 4; mi++) {
                const int r = warp_m + mi * 16 + q;
                const uint2 lo = *(const uint2*)&As[cur][r    ][col];  // (a0,a2)
                const uint2 hi = *(const uint2*)&As[cur][r + 8][col];  // (a1,a3)
                af[mi][0] = lo.x; af[mi][1] = hi.x;
                af[mi][2] = lo.y; af[mi][3] = hi.y;
            }
#pragma unroll
            for (int ni = 0; ni < 8; ni++) {
                const int rn = warp_n + ni * 8 + q;
                const uint2 bv = *(const uint2*)&Bs[cur][rn][col];
                uint32_t bf[2] = { bv.x, bv.y };
#pragma unroll
                for (int mi = 0; mi < 4; mi++)
                    mma8(acc[mi][ni], af[mi], bf);
            }
        }

        if (more) STS_TILE(cur ^ 1);
        __syncthreads();
    }

    // epilogue: c0,c1 at (row, 2kb..2kb+1); c2,c3 at (row+8, same cols)
#pragma unroll
    for (int mi = 0; mi < 4; mi++) {
        const int rlo = m0 + warp_m + mi * 16 + q;
        const int rhi = rlo + 8;
#pragma unroll
        for (int ni = 0; ni < 8; ni++) {
            const int col = n0 + warp_n + ni * 8 + 2 * kb;
            if (rlo < M) {
                const int cr = SCATTER_C ? tl[rlo] : rlo;
                float* cp = C + (size_t)cr * ldc + col;
                if (SCATTER_C) {
                    atomicAdd(cp,     acc[mi][ni][0]);
                    atomicAdd(cp + 1, acc[mi][ni][1]);
                } else {
                    *(float2*)cp = make_float2(acc[mi][ni][0], acc[mi][ni][1]);
                }
            }
            if (rhi < M) {
                const int cr = SCATTER_C ? tl[rhi] : rhi;
                float* cp = C + (size_t)cr * ldc + col;
                if (SCATTER_C) {
                    atomicAdd(cp,     acc[mi][ni][2]);
                    atomicAdd(cp + 1, acc[mi][ni][3]);
                } else {
                    *(float2*)cp = make_float2(acc[mi][ni][2], acc[mi][ni][3]);
                }
            }
        }
    }
#undef LDG_TILE
#undef STS_TILE
}

// ---------------- GEMM wrappers ---------------------------------------------
__global__ void __launch_bounds__(NTHR, 2)
gemm_shared1(const float* __restrict__ x, const float* __restrict__ sw1) {
    mma_core<false, false>(x, HH, sw1, HH, g_buf1, IS2, HH, TT, nullptr);
}

__global__ void __launch_bounds__(NTHR, 2)
gemm_shared2(const float* __restrict__ sw2, float* __restrict__ out) {
    mma_core<false, false>(g_buf2, ISH, sw2, ISH, out, HH, ISH, TT, nullptr);
}

__global__ void __launch_bounds__(NTHR, 2)
gemm_routed1(const float* __restrict__ x, const float* __restrict__ w1) {
    const int e = blockIdx.z;
    mma_core<true, false>(
        x, HH,
        w1 + (size_t)e * I2 * HH, HH,
        g_buf1 + (size_t)g_off[e] * I2, I2,
        HH, g_cnt[e], g_tok + e * TT);
}

__global__ void __launch_bounds__(NTHR, 2)
gemm_routed2(const float* __restrict__ w2, float* __restrict__ out) {
    const int e = blockIdx.z;
    mma_core<false, true>(
        g_buf2 + (size_t)g_off[e] * ID, ID,
        w2 + (size_t)e * HH * ID, ID,
        out, HH,
        ID, g_cnt[e], g_tok + e * TT);
}

// ---------------- launcher: kernel launches ONLY ----------------------------
extern "C" void kernel_launch(void* const* d_in, const int* in_sizes, int n_in,
                              void* d_out, int out_size) {
    const float* x   = (const float*)d_in[0];   // (1,2048,2048)
    const float* gw  = (const float*)d_in[1];   // (16,2048)
    const float* w1  = (const float*)d_in[2];   // (16,2816,2048)
    const float* w2  = (const float*)d_in[3];   // (16,2048,1408)
    const float* sw1 = (const float*)d_in[4];   // (5632,2048)
    const float* sw2 = (const float*)d_in[5];   // (2048,2816)
    float* out = (float*)d_out;                 // (1,2048,2048) fp32
    (void)in_sizes; (void)n_in; (void)out_size;

    // 1) routing
    zero_cnt_kernel<<<1, 32>>>();
    gate_kernel<<<TT, 256>>>(x, gw);
    prefix_kernel<<<1, 32>>>();

    // 2) shared FFN
    gemm_shared1<<<dim3(IS2 / NB, TT / MB, 1), NTHR>>>(x, sw1);
    act_shared_kernel<<<TT, 256>>>();
    gemm_shared2<<<dim3(HH / NB, TT / MB, 1), NTHR>>>(sw2, out);

    // 3) routed path
    gemm_routed1<<<dim3(I2 / NB, TT / MB, NE), NTHR>>>(x, w1);
    act_routed_kernel<<<dim3(TT, NE), 256>>>();
    gemm_routed2<<<dim3(HH / NB, TT / MB, NE), NTHR>>>(w2, out);
}